// round 11
// baseline (speedup 1.0000x reference)
#include <cuda_runtime.h>
#include <cuda_fp16.h>
#include <cstdint>
#include <cstddef>

#define NN   50000
#define NE   640000
#define INF_ 512
#define HIDF 128
#define NG   256
#define SPLIT 24960   // 195 * 128

// ---------------- device scratch (no allocations allowed) ----------------
__device__ int   g_cnt[NN];          // zero at load; k_scan restores to zero each launch
__device__ float g_dinv[NN];
__device__ int   g_rowptr[NN + 1];
__device__ int   g_rank[NE];
__device__ int   g_src[NE];
__device__ __half g_g1[(size_t)NN * HIDF];    // gemm outputs (fp16), reused both layers
__device__ __half g_h1h[(size_t)NN * HIDF];   // layer-1 agg output (fp16)
// transposed fp16 weights: Wt[n][k] = W[k][n]
__device__ __half g_w1h[128 * 512];
__device__ __half g_w2h[128 * 128];

// ---------------- helpers ----------------
__device__ __forceinline__ uint32_t smem_u32(const void* p) {
    uint32_t a;
    asm("{ .reg .u64 t; cvta.to.shared.u64 t, %1; cvt.u32.u64 %0, t; }" : "=r"(a) : "l"(p));
    return a;
}
__device__ __forceinline__ void ldsm_x4(uint32_t& r0, uint32_t& r1, uint32_t& r2, uint32_t& r3,
                                        uint32_t addr) {
    asm volatile("ldmatrix.sync.aligned.m8n8.x4.shared.b16 {%0,%1,%2,%3}, [%4];"
                 : "=r"(r0), "=r"(r1), "=r"(r2), "=r"(r3) : "r"(addr));
}
__device__ __forceinline__ void mma_f16(float* c, const uint32_t* a, const uint32_t* b) {
    asm volatile(
        "mma.sync.aligned.m16n8k16.row.col.f32.f16.f16.f32 "
        "{%0,%1,%2,%3}, {%4,%5,%6,%7}, {%8,%9}, {%0,%1,%2,%3};"
        : "+f"(c[0]), "+f"(c[1]), "+f"(c[2]), "+f"(c[3])
        : "r"(a[0]), "r"(a[1]), "r"(a[2]), "r"(a[3]), "r"(b[0]), "r"(b[1]));
}

// ---------------- preprocessing ----------------
// coalesced smem-tiled transpose + fp16 cast of W1 (64 tiles) and W2 (16 tiles)
__global__ __launch_bounds__(256) void k_prepw(const float* __restrict__ W1,
                                               const float* __restrict__ W2) {
    __shared__ float tile[32][33];
    int b = blockIdx.x;
    int tx = threadIdx.x & 31, ty = threadIdx.x >> 5;  // 32 x 8
    const float* W; __half* O; int K, tk, tn;
    if (b < 64) { W = W1; O = g_w1h; K = 512; tk = b >> 2; tn = b & 3; }
    else        { W = W2; O = g_w2h; K = 128; tk = (b - 64) >> 2; tn = (b - 64) & 3; }
    #pragma unroll
    for (int i = 0; i < 4; i++) {
        int r = ty + i * 8;
        tile[r][tx] = W[(size_t)(tk * 32 + r) * 128 + tn * 32 + tx];
    }
    __syncthreads();
    #pragma unroll
    for (int i = 0; i < 4; i++) {
        int r = ty + i * 8;   // n within tile
        O[(size_t)(tn * 32 + r) * K + tk * 32 + tx] = __float2half_rn(tile[tx][r]);
    }
}

// count + record per-edge rank within destination (atomicAdd return value), 2 edges/thread
__global__ void k_count(const int* __restrict__ col) {
    int t = blockIdx.x * blockDim.x + threadIdx.x;
    if (t < NE / 2) {
        int2 c2 = ((const int2*)col)[t];
        int2 r;
        r.x = atomicAdd(&g_cnt[c2.x], 1);
        r.y = atomicAdd(&g_cnt[c2.y], 1);
        ((int2*)g_rank)[t] = r;
    }
}

// single-block scan, smem-staged for fully coalesced global access.
// Also restores g_cnt to zero for the next launch (invariant: zero at entry).
__global__ __launch_bounds__(1024) void k_scan() {
    extern __shared__ int sc[];   // NN ints = 200 000 B
    __shared__ int wsum[32];
    int t = threadIdx.x, lane = t & 31, w = t >> 5;
    for (int i = t; i < NN; i += 1024) {
        int c = g_cnt[i];
        sc[i] = c;
        g_dinv[i] = rsqrtf((float)(c + 1));  // +1 self-loop
        g_cnt[i] = 0;                        // restore invariant for next launch
    }
    __syncthreads();
    const int SEG = (NN + 1023) / 1024;  // 49
    int s0 = t * SEG, s1 = s0 + SEG;
    if (s1 > NN) s1 = NN;
    if (s0 > NN) s0 = NN;
    int s = 0;
    for (int i = s0; i < s1; i++) s += sc[i];
    int v = s;
    #pragma unroll
    for (int o = 1; o < 32; o <<= 1) {
        int u = __shfl_up_sync(0xFFFFFFFFu, v, o);
        if (lane >= o) v += u;
    }
    if (lane == 31) wsum[w] = v;
    __syncthreads();
    if (w == 0) {
        int x = wsum[lane];
        #pragma unroll
        for (int o = 1; o < 32; o <<= 1) {
            int u = __shfl_up_sync(0xFFFFFFFFu, x, o);
            if (lane >= o) x += u;
        }
        wsum[lane] = x;
    }
    __syncthreads();
    int P = v - s + (w > 0 ? wsum[w - 1] : 0);
    for (int i = s0; i < s1; i++) {
        int c = sc[i];
        sc[i] = P;     // in-place exclusive prefix
        P += c;
    }
    __syncthreads();
    for (int i = t; i < NN; i += 1024) g_rowptr[i] = sc[i];
    if (t == 0) g_rowptr[NN] = wsum[31];
}

// atomic-free fill using precomputed ranks, 2 edges/thread
__global__ void k_fill(const int* __restrict__ row, const int* __restrict__ col) {
    int t = blockIdx.x * blockDim.x + threadIdx.x;
    if (t < NE / 2) {
        int2 r2 = ((const int2*)row)[t];
        int2 c2 = ((const int2*)col)[t];
        int2 k2 = ((const int2*)g_rank)[t];
        g_src[g_rowptr[c2.x] + k2.x] = r2.x;
        g_src[g_rowptr[c2.y] + k2.y] = r2.y;
    }
}

// ---------------- HMMA GEMM: C[M,128] = A[M,K] @ Wt^T, fp16 out ----------------
#define ASTRIDE 40  // fp16 elems per smem row (80 B), conflict-free ldmatrix

template <bool F32A>
__device__ __forceinline__ void gemm_body(const void* __restrict__ Aptr,
                                          const __half* __restrict__ Bh,
                                          __half* __restrict__ C,
                                          int M, int K, int base) {
    __shared__ __half sAh[128 * ASTRIDE];
    __shared__ __half sBh[128 * ASTRIDE];
    const int tid = threadIdx.x;
    const int wid = tid >> 5, lane = tid & 31;
    const int wm = (wid >> 1) * 32;
    const int wn = (wid & 1) * 64;
    const int g = lane >> 2, tig = lane & 3;
    const int row0 = base + blockIdx.x * 128;

    const uint32_t uAh = smem_u32(sAh);
    const uint32_t uBh = smem_u32(sBh);

    float c[2][8][4];
    #pragma unroll
    for (int mt = 0; mt < 2; mt++)
        #pragma unroll
        for (int nt = 0; nt < 8; nt++)
            #pragma unroll
            for (int q = 0; q < 4; q++) c[mt][nt][q] = 0.f;

    const int nch = K >> 5;

    float4 pa[4];
    uint4 pah[2];
    uint4 pbh[2];

    if (F32A) {
        const float* A = (const float*)Aptr;
        #pragma unroll
        for (int i = 0; i < 4; i++) {
            int q = i * 256 + tid;
            int r = q >> 3, c4 = q & 7;
            int gr = row0 + r;
            pa[i] = (gr < M) ? *(const float4*)(A + (size_t)gr * K + c4 * 4)
                             : make_float4(0.f, 0.f, 0.f, 0.f);
        }
    } else {
        const __half* Ah = (const __half*)Aptr;
        #pragma unroll
        for (int i = 0; i < 2; i++) {
            int q = i * 256 + tid;
            int r = q >> 2, c16 = q & 3;
            int gr = row0 + r;
            pah[i] = (gr < M) ? *(const uint4*)(Ah + (size_t)gr * K + c16 * 8)
                              : make_uint4(0, 0, 0, 0);
        }
    }
    #pragma unroll
    for (int i = 0; i < 2; i++) {
        int q = i * 256 + tid;
        int r = q >> 2, c16 = q & 3;
        pbh[i] = *(const uint4*)(Bh + (size_t)r * K + c16 * 8);
    }

    for (int ch = 0; ch < nch; ch++) {
        if (F32A) {
            #pragma unroll
            for (int i = 0; i < 4; i++) {
                int q = i * 256 + tid;
                int r = q >> 3, c4 = q & 7;
                float4 v = pa[i];
                __half2 h0 = __floats2half2_rn(v.x, v.y);
                __half2 h1 = __floats2half2_rn(v.z, v.w);
                int e = r * ASTRIDE + c4 * 4;
                *(uint32_t*)((char*)sAh + e * 2)     = *(uint32_t*)&h0;
                *(uint32_t*)((char*)sAh + e * 2 + 4) = *(uint32_t*)&h1;
            }
        } else {
            #pragma unroll
            for (int i = 0; i < 2; i++) {
                int q = i * 256 + tid;
                int r = q >> 2, c16 = q & 3;
                int e = r * ASTRIDE + c16 * 8;
                *(uint4*)((char*)sAh + e * 2) = pah[i];
            }
        }
        #pragma unroll
        for (int i = 0; i < 2; i++) {
            int q = i * 256 + tid;
            int r = q >> 2, c16 = q & 3;
            int e = r * ASTRIDE + c16 * 8;
            *(uint4*)((char*)sBh + e * 2) = pbh[i];
        }
        __syncthreads();

        if (ch + 1 < nch) {
            int k0 = (ch + 1) << 5;
            if (F32A) {
                const float* A = (const float*)Aptr;
                #pragma unroll
                for (int i = 0; i < 4; i++) {
                    int q = i * 256 + tid;
                    int r = q >> 3, c4 = q & 7;
                    int gr = row0 + r;
                    pa[i] = (gr < M) ? *(const float4*)(A + (size_t)gr * K + k0 + c4 * 4)
                                     : make_float4(0.f, 0.f, 0.f, 0.f);
                }
            } else {
                const __half* Ah = (const __half*)Aptr;
                #pragma unroll
                for (int i = 0; i < 2; i++) {
                    int q = i * 256 + tid;
                    int r = q >> 2, c16 = q & 3;
                    int gr = row0 + r;
                    pah[i] = (gr < M) ? *(const uint4*)(Ah + (size_t)gr * K + k0 + c16 * 8)
                                      : make_uint4(0, 0, 0, 0);
                }
            }
            #pragma unroll
            for (int i = 0; i < 2; i++) {
                int q = i * 256 + tid;
                int r = q >> 2, c16 = q & 3;
                pbh[i] = *(const uint4*)(Bh + (size_t)r * K + k0 + c16 * 8);
            }
        }

        #pragma unroll
        for (int ks = 0; ks < 2; ks++) {
            const int kc = ks * 16 + ((lane & 16) ? 8 : 0);
            uint32_t ah[2][4];
            #pragma unroll
            for (int mt = 0; mt < 2; mt++) {
                int r = wm + mt * 16 + (lane & 15);
                uint32_t off = (uint32_t)(r * ASTRIDE + kc) * 2;
                ldsm_x4(ah[mt][0], ah[mt][1], ah[mt][2], ah[mt][3], uAh + off);
            }
            uint32_t bh[8][2];
            const int kcb = ks * 16 + ((lane & 8) ? 8 : 0);
            #pragma unroll
            for (int nt4 = 0; nt4 < 4; nt4++) {
                int n = wn + nt4 * 16 + ((lane & 7) | ((lane & 16) ? 8 : 0));
                uint32_t off = (uint32_t)(n * ASTRIDE + kcb) * 2;
                ldsm_x4(bh[2 * nt4][0], bh[2 * nt4][1], bh[2 * nt4 + 1][0], bh[2 * nt4 + 1][1],
                        uBh + off);
            }
            #pragma unroll
            for (int mt = 0; mt < 2; mt++)
                #pragma unroll
                for (int nt = 0; nt < 8; nt++)
                    mma_f16(c[mt][nt], ah[mt], bh[nt]);
        }
        __syncthreads();
    }

    #pragma unroll
    for (int mt = 0; mt < 2; mt++) {
        int gr0 = row0 + wm + mt * 16 + g;
        int gr1 = gr0 + 8;
        #pragma unroll
        for (int nt = 0; nt < 8; nt++) {
            int cc = wn + nt * 8 + 2 * tig;
            if (gr0 < M) *(__half2*)(C + (size_t)gr0 * 128 + cc) = __floats2half2_rn(c[mt][nt][0], c[mt][nt][1]);
            if (gr1 < M) *(__half2*)(C + (size_t)gr1 * 128 + cc) = __floats2half2_rn(c[mt][nt][2], c[mt][nt][3]);
        }
    }
}

__global__ __launch_bounds__(256) void gemm_f32A(const float* __restrict__ A,
                                                 const __half* __restrict__ Bh,
                                                 __half* __restrict__ C, int M, int K) {
    gemm_body<true>(A, Bh, C, M, K, 0);
}
__global__ __launch_bounds__(256) void gemm_f16A(const __half* __restrict__ Ah,
                                                 const __half* __restrict__ Bh,
                                                 __half* __restrict__ C, int M, int K, int base) {
    gemm_body<false>(Ah, Bh, C, M, K, base);
}

// ---------------- aggregation: one warp per node, CSR gather of fp16 rows ----------------
__device__ __forceinline__ float4 load_row4(const __half* __restrict__ in, int node, int lane) {
    uint2 pv = ((const uint2*)(in + (size_t)node * HIDF))[lane];  // 4 halves
    float2 fa = __half22float2(*(__half2*)&pv.x);
    float2 fb = __half22float2(*(__half2*)&pv.y);
    return make_float4(fa.x, fa.y, fb.x, fb.y);
}

// shared agg core: returns biased (pre-activation) accumulator
__device__ __forceinline__ float4 agg_core(const __half* __restrict__ in, int node, int lane,
                                           const float* __restrict__ bias) {
    float dn = g_dinv[node];
    float4 v = load_row4(in, node, lane);
    float s = dn * dn;
    float4 acc = make_float4(v.x * s, v.y * s, v.z * s, v.w * s);
    float4 acc2 = make_float4(0.f, 0.f, 0.f, 0.f);
    int beg = g_rowptr[node], end = g_rowptr[node + 1];
    int j = beg;
    for (; j + 1 < end; j += 2) {       // 2 rows in flight
        int sa = g_src[j], sb = g_src[j + 1];
        float wa = g_dinv[sa] * dn, wb = g_dinv[sb] * dn;
        float4 ua = load_row4(in, sa, lane);
        float4 ub = load_row4(in, sb, lane);
        acc.x += ua.x * wa;  acc.y += ua.y * wa;
        acc.z += ua.z * wa;  acc.w += ua.w * wa;
        acc2.x += ub.x * wb; acc2.y += ub.y * wb;
        acc2.z += ub.z * wb; acc2.w += ub.w * wb;
    }
    if (j < end) {
        int sa = g_src[j];
        float wa = g_dinv[sa] * dn;
        float4 ua = load_row4(in, sa, lane);
        acc.x += ua.x * wa; acc.y += ua.y * wa;
        acc.z += ua.z * wa; acc.w += ua.w * wa;
    }
    float4 b = ((const float4*)bias)[lane];
    acc.x += acc2.x + b.x; acc.y += acc2.y + b.y;
    acc.z += acc2.z + b.z; acc.w += acc2.w + b.w;
    return acc;
}

// Layer 1: relu, emit fp16 (feeds gemm_f16A); node range [base, base+8*gridDim)
__global__ __launch_bounds__(256) void k_agg_f16(const __half* __restrict__ in,
                                                 __half* __restrict__ outh,
                                                 const float* __restrict__ bias, int base) {
    int warp = base + ((blockIdx.x * blockDim.x + threadIdx.x) >> 5);
    int lane = threadIdx.x & 31;
    if (warp >= NN) return;
    float4 acc = agg_core(in, warp, lane, bias);
    acc.x = fmaxf(acc.x, 0.f); acc.y = fmaxf(acc.y, 0.f);
    acc.z = fmaxf(acc.z, 0.f); acc.w = fmaxf(acc.w, 0.f);
    __half2 h0 = __floats2half2_rn(acc.x, acc.y);
    __half2 h1 = __floats2half2_rn(acc.z, acc.w);
    uint2 ph = make_uint2(*(uint32_t*)&h0, *(uint32_t*)&h1);
    ((uint2*)(outh + (size_t)warp * HIDF))[lane] = ph;
}

// Layer 2: fp32 out (final h), no relu
__global__ __launch_bounds__(256) void k_agg_f32(const __half* __restrict__ in,
                                                 float* __restrict__ out,
                                                 const float* __restrict__ bias) {
    int warp = (blockIdx.x * blockDim.x + threadIdx.x) >> 5;
    int lane = threadIdx.x & 31;
    if (warp >= NN) return;
    float4 acc = agg_core(in, warp, lane, bias);
    ((float4*)(out + (size_t)warp * HIDF))[lane] = acc;
}

// ---------------- global_add_pool: batch is sorted -> segmented sum ----------------
__global__ void k_pool(const float* __restrict__ h, const int* __restrict__ batch,
                       float* __restrict__ out) {
    int g = blockIdx.x;
    int t = threadIdx.x;
    int a = 0, b = NN;
    while (a < b) { int m = (a + b) >> 1; if (batch[m] < g) a = m + 1; else b = m; }
    int s = a;
    a = 0; b = NN;
    while (a < b) { int m = (a + b) >> 1; if (batch[m] < g + 1) a = m + 1; else b = m; }
    int e = a;
    float a0 = 0.f, a1 = 0.f, a2 = 0.f, a3 = 0.f;
    int n = s;
    for (; n + 3 < e; n += 4) {          // 4 rows in flight
        a0 += h[(size_t)n * HIDF + t];
        a1 += h[(size_t)(n + 1) * HIDF + t];
        a2 += h[(size_t)(n + 2) * HIDF + t];
        a3 += h[(size_t)(n + 3) * HIDF + t];
    }
    for (; n < e; n++) a0 += h[(size_t)n * HIDF + t];
    out[(size_t)g * HIDF + t] = (a0 + a1) + (a2 + a3);
}

// ---------------- launch ----------------
extern "C" void kernel_launch(void* const* d_in, const int* in_sizes, int n_in,
                              void* d_out, int out_size) {
    const float* x     = (const float*)d_in[0];
    const float* W1    = (const float*)d_in[1];
    const float* b1    = (const float*)d_in[2];
    const float* W2    = (const float*)d_in[3];
    const float* b2    = (const float*)d_in[4];
    const int*   ei    = (const int*)d_in[5];
    const int*   batch = (const int*)d_in[6];
    const int* row = ei;        // edge_index[0] = source
    const int* col = ei + NE;   // edge_index[1] = target

    float* out_hs = (float*)d_out;
    float* out_h  = (float*)d_out + (size_t)NG * HIDF;

    __half *g1, *h1h, *w1h, *w2h;
    cudaGetSymbolAddress((void**)&g1, g_g1);
    cudaGetSymbolAddress((void**)&h1h, g_h1h);
    cudaGetSymbolAddress((void**)&w1h, g_w1h);
    cudaGetSymbolAddress((void**)&w2h, g_w2h);

    cudaFuncSetAttribute(k_scan, cudaFuncAttributeMaxDynamicSharedMemorySize, NN * 4);

    // fork-join streams (created per call; see round-10 note on lifetime)
    cudaStream_t s2;
    cudaStreamCreateWithFlags(&s2, cudaStreamNonBlocking);
    cudaEvent_t evFork, evJoin, evA1lo, evG2lo;
    cudaEventCreateWithFlags(&evFork, cudaEventDisableTiming);
    cudaEventCreateWithFlags(&evJoin, cudaEventDisableTiming);
    cudaEventCreateWithFlags(&evA1lo, cudaEventDisableTiming);
    cudaEventCreateWithFlags(&evG2lo, cudaEventDisableTiming);

    cudaEventRecord(evFork, 0);
    cudaStreamWaitEvent(s2, evFork, 0);

    // branch B (s2): CSR build
    k_count<<<(NE / 2 + 255) / 256, 256, 0, s2>>>(col);
    k_scan<<<1, 1024, NN * 4, s2>>>();
    k_fill<<<(NE / 2 + 255) / 256, 256, 0, s2>>>(row, col);
    cudaEventRecord(evJoin, s2);

    // branch A (origin): weights + layer-1 GEMM
    k_prepw<<<80, 256>>>(W1, W2);
    gemm_f32A<<<(NN + 127) / 128, 256>>>(x, w1h, g1, NN, INF_);

    // join: aggregation needs CSR
    cudaStreamWaitEvent(0, evJoin, 0);

    // pipelined agg1 / gemm2: lo nodes [0,SPLIT), hi nodes [SPLIT,NN)
    k_agg_f16<<<SPLIT / 8, 256>>>(g1, h1h, b1, 0);              // agg1_lo
    cudaEventRecord(evA1lo, 0);
    cudaStreamWaitEvent(s2, evA1lo, 0);
    gemm_f16A<<<SPLIT / 128, 256, 0, s2>>>(h1h, w2h, g1, NN, HIDF, 0);   // gemm2_lo ∥ agg1_hi
    cudaEventRecord(evG2lo, s2);
    k_agg_f16<<<(NN - SPLIT + 7) / 8, 256>>>(g1, h1h, b1, SPLIT);        // agg1_hi
    gemm_f16A<<<(NN - SPLIT + 127) / 128, 256>>>(h1h, w2h, g1, NN, HIDF, SPLIT);  // gemm2_hi
    cudaStreamWaitEvent(0, evG2lo, 0);

    // layer-2 aggregation + pooling
    k_agg_f32<<<(NN + 7) / 8, 256>>>(g1, out_h, b2);
    k_pool<<<NG, 128>>>(out_h, batch, out_hs);
}

// round 12
// speedup vs baseline: 1.2462x; 1.2462x over previous
#include <cuda_runtime.h>
#include <cuda_fp16.h>
#include <cstdint>
#include <cstddef>

#define NN   50000
#define NE   640000
#define INF_ 512
#define HIDF 128
#define NG   256

// ---------------- device scratch (no allocations allowed) ----------------
__device__ int   g_cnt[NN];          // zero at load; k_scan restores to zero each launch
__device__ float g_dinv[NN];
__device__ int   g_rowptr[NN + 1];
__device__ int   g_rank[NE];
__device__ int   g_src[NE];
__device__ __half g_g1[(size_t)NN * HIDF];    // gemm outputs (fp16), reused both layers
__device__ __half g_h1h[(size_t)NN * HIDF];   // layer-1 agg output (fp16)
// transposed fp16 weights: Wt[n][k] = W[k][n]
__device__ __half g_w1h[128 * 512];
__device__ __half g_w2h[128 * 128];

// ---------------- helpers ----------------
__device__ __forceinline__ uint32_t smem_u32(const void* p) {
    uint32_t a;
    asm("{ .reg .u64 t; cvta.to.shared.u64 t, %1; cvt.u32.u64 %0, t; }" : "=r"(a) : "l"(p));
    return a;
}
__device__ __forceinline__ void ldsm_x4(uint32_t& r0, uint32_t& r1, uint32_t& r2, uint32_t& r3,
                                        uint32_t addr) {
    asm volatile("ldmatrix.sync.aligned.m8n8.x4.shared.b16 {%0,%1,%2,%3}, [%4];"
                 : "=r"(r0), "=r"(r1), "=r"(r2), "=r"(r3) : "r"(addr));
}
__device__ __forceinline__ void mma_f16(float* c, const uint32_t* a, const uint32_t* b) {
    asm volatile(
        "mma.sync.aligned.m16n8k16.row.col.f32.f16.f16.f32 "
        "{%0,%1,%2,%3}, {%4,%5,%6,%7}, {%8,%9}, {%0,%1,%2,%3};"
        : "+f"(c[0]), "+f"(c[1]), "+f"(c[2]), "+f"(c[3])
        : "r"(a[0]), "r"(a[1]), "r"(a[2]), "r"(a[3]), "r"(b[0]), "r"(b[1]));
}

// ---------------- preprocessing ----------------
// transpose/cast weights (g_cnt zeroing handled by k_scan's restore)
__global__ void k_prepw(const float* __restrict__ W1, const float* __restrict__ W2) {
    int i = blockIdx.x * blockDim.x + threadIdx.x;
    if (i < 128 * 512) {
        int n = i >> 9, k = i & 511;
        g_w1h[i] = __float2half_rn(W1[k * 128 + n]);
    }
    if (i < 128 * 128) {
        int n = i >> 7, k = i & 127;
        g_w2h[i] = __float2half_rn(W2[k * 128 + n]);
    }
}

// count + record per-edge rank within destination (atomicAdd return value), 2 edges/thread
__global__ void k_count(const int* __restrict__ col) {
    int t = blockIdx.x * blockDim.x + threadIdx.x;
    if (t < NE / 2) {
        int2 c2 = ((const int2*)col)[t];
        int2 r;
        r.x = atomicAdd(&g_cnt[c2.x], 1);
        r.y = atomicAdd(&g_cnt[c2.y], 1);
        ((int2*)g_rank)[t] = r;
    }
}

// single-block scan, smem-staged for fully coalesced global access.
// Also restores g_cnt to zero for the next launch (invariant: zero at entry).
__global__ __launch_bounds__(1024) void k_scan() {
    extern __shared__ int sc[];   // NN ints = 200 000 B
    __shared__ int wsum[32];
    int t = threadIdx.x, lane = t & 31, w = t >> 5;
    for (int i = t; i < NN; i += 1024) {
        int c = g_cnt[i];
        sc[i] = c;
        g_dinv[i] = rsqrtf((float)(c + 1));  // +1 self-loop
        g_cnt[i] = 0;                        // restore invariant for next launch
    }
    __syncthreads();
    const int SEG = (NN + 1023) / 1024;  // 49
    int s0 = t * SEG, s1 = s0 + SEG;
    if (s1 > NN) s1 = NN;
    if (s0 > NN) s0 = NN;
    int s = 0;
    for (int i = s0; i < s1; i++) s += sc[i];
    int v = s;
    #pragma unroll
    for (int o = 1; o < 32; o <<= 1) {
        int u = __shfl_up_sync(0xFFFFFFFFu, v, o);
        if (lane >= o) v += u;
    }
    if (lane == 31) wsum[w] = v;
    __syncthreads();
    if (w == 0) {
        int x = wsum[lane];
        #pragma unroll
        for (int o = 1; o < 32; o <<= 1) {
            int u = __shfl_up_sync(0xFFFFFFFFu, x, o);
            if (lane >= o) x += u;
        }
        wsum[lane] = x;
    }
    __syncthreads();
    int P = v - s + (w > 0 ? wsum[w - 1] : 0);
    for (int i = s0; i < s1; i++) {
        int c = sc[i];
        sc[i] = P;     // in-place exclusive prefix
        P += c;
    }
    __syncthreads();
    for (int i = t; i < NN; i += 1024) g_rowptr[i] = sc[i];
    if (t == 0) g_rowptr[NN] = wsum[31];
}

// atomic-free fill using precomputed ranks, 2 edges/thread
__global__ void k_fill(const int* __restrict__ row, const int* __restrict__ col) {
    int t = blockIdx.x * blockDim.x + threadIdx.x;
    if (t < NE / 2) {
        int2 r2 = ((const int2*)row)[t];
        int2 c2 = ((const int2*)col)[t];
        int2 k2 = ((const int2*)g_rank)[t];
        g_src[g_rowptr[c2.x] + k2.x] = r2.x;
        g_src[g_rowptr[c2.y] + k2.y] = r2.y;
    }
}

// ---------------- HMMA GEMM: C[M,128] = A[M,K] @ Wt^T, fp16 out ----------------
#define ASTRIDE 40  // fp16 elems per smem row (80 B), conflict-free ldmatrix

template <bool F32A>
__device__ __forceinline__ void gemm_body(const void* __restrict__ Aptr,
                                          const __half* __restrict__ Bh,
                                          __half* __restrict__ C,
                                          int M, int K) {
    __shared__ __half sAh[128 * ASTRIDE];
    __shared__ __half sBh[128 * ASTRIDE];
    const int tid = threadIdx.x;
    const int wid = tid >> 5, lane = tid & 31;
    const int wm = (wid >> 1) * 32;
    const int wn = (wid & 1) * 64;
    const int g = lane >> 2, tig = lane & 3;
    const int row0 = blockIdx.x * 128;

    const uint32_t uAh = smem_u32(sAh);
    const uint32_t uBh = smem_u32(sBh);

    float c[2][8][4];
    #pragma unroll
    for (int mt = 0; mt < 2; mt++)
        #pragma unroll
        for (int nt = 0; nt < 8; nt++)
            #pragma unroll
            for (int q = 0; q < 4; q++) c[mt][nt][q] = 0.f;

    const int nch = K >> 5;

    float4 pa[4];
    uint4 pah[2];
    uint4 pbh[2];

    if (F32A) {
        const float* A = (const float*)Aptr;
        #pragma unroll
        for (int i = 0; i < 4; i++) {
            int q = i * 256 + tid;
            int r = q >> 3, c4 = q & 7;
            int gr = row0 + r;
            pa[i] = (gr < M) ? *(const float4*)(A + (size_t)gr * K + c4 * 4)
                             : make_float4(0.f, 0.f, 0.f, 0.f);
        }
    } else {
        const __half* Ah = (const __half*)Aptr;
        #pragma unroll
        for (int i = 0; i < 2; i++) {
            int q = i * 256 + tid;
            int r = q >> 2, c16 = q & 3;
            int gr = row0 + r;
            pah[i] = (gr < M) ? *(const uint4*)(Ah + (size_t)gr * K + c16 * 8)
                              : make_uint4(0, 0, 0, 0);
        }
    }
    #pragma unroll
    for (int i = 0; i < 2; i++) {
        int q = i * 256 + tid;
        int r = q >> 2, c16 = q & 3;
        pbh[i] = *(const uint4*)(Bh + (size_t)r * K + c16 * 8);
    }

    for (int ch = 0; ch < nch; ch++) {
        if (F32A) {
            #pragma unroll
            for (int i = 0; i < 4; i++) {
                int q = i * 256 + tid;
                int r = q >> 3, c4 = q & 7;
                float4 v = pa[i];
                __half2 h0 = __floats2half2_rn(v.x, v.y);
                __half2 h1 = __floats2half2_rn(v.z, v.w);
                int e = r * ASTRIDE + c4 * 4;
                *(uint32_t*)((char*)sAh + e * 2)     = *(uint32_t*)&h0;
                *(uint32_t*)((char*)sAh + e * 2 + 4) = *(uint32_t*)&h1;
            }
        } else {
            #pragma unroll
            for (int i = 0; i < 2; i++) {
                int q = i * 256 + tid;
                int r = q >> 2, c16 = q & 3;
                int e = r * ASTRIDE + c16 * 8;
                *(uint4*)((char*)sAh + e * 2) = pah[i];
            }
        }
        #pragma unroll
        for (int i = 0; i < 2; i++) {
            int q = i * 256 + tid;
            int r = q >> 2, c16 = q & 3;
            int e = r * ASTRIDE + c16 * 8;
            *(uint4*)((char*)sBh + e * 2) = pbh[i];
        }
        __syncthreads();

        if (ch + 1 < nch) {
            int k0 = (ch + 1) << 5;
            if (F32A) {
                const float* A = (const float*)Aptr;
                #pragma unroll
                for (int i = 0; i < 4; i++) {
                    int q = i * 256 + tid;
                    int r = q >> 3, c4 = q & 7;
                    int gr = row0 + r;
                    pa[i] = (gr < M) ? *(const float4*)(A + (size_t)gr * K + k0 + c4 * 4)
                                     : make_float4(0.f, 0.f, 0.f, 0.f);
                }
            } else {
                const __half* Ah = (const __half*)Aptr;
                #pragma unroll
                for (int i = 0; i < 2; i++) {
                    int q = i * 256 + tid;
                    int r = q >> 2, c16 = q & 3;
                    int gr = row0 + r;
                    pah[i] = (gr < M) ? *(const uint4*)(Ah + (size_t)gr * K + k0 + c16 * 8)
                                      : make_uint4(0, 0, 0, 0);
                }
            }
            #pragma unroll
            for (int i = 0; i < 2; i++) {
                int q = i * 256 + tid;
                int r = q >> 2, c16 = q & 3;
                pbh[i] = *(const uint4*)(Bh + (size_t)r * K + k0 + c16 * 8);
            }
        }

        #pragma unroll
        for (int ks = 0; ks < 2; ks++) {
            const int kc = ks * 16 + ((lane & 16) ? 8 : 0);
            uint32_t ah[2][4];
            #pragma unroll
            for (int mt = 0; mt < 2; mt++) {
                int r = wm + mt * 16 + (lane & 15);
                uint32_t off = (uint32_t)(r * ASTRIDE + kc) * 2;
                ldsm_x4(ah[mt][0], ah[mt][1], ah[mt][2], ah[mt][3], uAh + off);
            }
            uint32_t bh[8][2];
            const int kcb = ks * 16 + ((lane & 8) ? 8 : 0);
            #pragma unroll
            for (int nt4 = 0; nt4 < 4; nt4++) {
                int n = wn + nt4 * 16 + ((lane & 7) | ((lane & 16) ? 8 : 0));
                uint32_t off = (uint32_t)(n * ASTRIDE + kcb) * 2;
                ldsm_x4(bh[2 * nt4][0], bh[2 * nt4][1], bh[2 * nt4 + 1][0], bh[2 * nt4 + 1][1],
                        uBh + off);
            }
            #pragma unroll
            for (int mt = 0; mt < 2; mt++)
                #pragma unroll
                for (int nt = 0; nt < 8; nt++)
                    mma_f16(c[mt][nt], ah[mt], bh[nt]);
        }
        __syncthreads();
    }

    #pragma unroll
    for (int mt = 0; mt < 2; mt++) {
        int gr0 = row0 + wm + mt * 16 + g;
        int gr1 = gr0 + 8;
        #pragma unroll
        for (int nt = 0; nt < 8; nt++) {
            int cc = wn + nt * 8 + 2 * tig;
            if (gr0 < M) *(__half2*)(C + (size_t)gr0 * 128 + cc) = __floats2half2_rn(c[mt][nt][0], c[mt][nt][1]);
            if (gr1 < M) *(__half2*)(C + (size_t)gr1 * 128 + cc) = __floats2half2_rn(c[mt][nt][2], c[mt][nt][3]);
        }
    }
}

__global__ __launch_bounds__(256) void gemm_f32A(const float* __restrict__ A,
                                                 const __half* __restrict__ Bh,
                                                 __half* __restrict__ C, int M, int K) {
    gemm_body<true>(A, Bh, C, M, K);
}
__global__ __launch_bounds__(256) void gemm_f16A(const __half* __restrict__ Ah,
                                                 const __half* __restrict__ Bh,
                                                 __half* __restrict__ C, int M, int K) {
    gemm_body<false>(Ah, Bh, C, M, K);
}

// ---------------- aggregation: one warp per node, CSR gather of fp16 rows ----------------
__device__ __forceinline__ float4 load_row4(const __half* __restrict__ in, int node, int lane) {
    uint2 pv = ((const uint2*)(in + (size_t)node * HIDF))[lane];  // 4 halves
    float2 fa = __half22float2(*(__half2*)&pv.x);
    float2 fb = __half22float2(*(__half2*)&pv.y);
    return make_float4(fa.x, fa.y, fb.x, fb.y);
}

// shared agg core: returns biased (pre-activation) accumulator; 2 gather rows in flight
__device__ __forceinline__ float4 agg_core(const __half* __restrict__ in, int node, int lane,
                                           const float* __restrict__ bias) {
    float dn = g_dinv[node];
    float4 v = load_row4(in, node, lane);
    float s = dn * dn;
    float4 acc = make_float4(v.x * s, v.y * s, v.z * s, v.w * s);
    float4 acc2 = make_float4(0.f, 0.f, 0.f, 0.f);
    int beg = g_rowptr[node], end = g_rowptr[node + 1];
    int j = beg;
    for (; j + 1 < end; j += 2) {
        int sa = g_src[j], sb = g_src[j + 1];
        float wa = g_dinv[sa] * dn, wb = g_dinv[sb] * dn;
        float4 ua = load_row4(in, sa, lane);
        float4 ub = load_row4(in, sb, lane);
        acc.x += ua.x * wa;  acc.y += ua.y * wa;
        acc.z += ua.z * wa;  acc.w += ua.w * wa;
        acc2.x += ub.x * wb; acc2.y += ub.y * wb;
        acc2.z += ub.z * wb; acc2.w += ub.w * wb;
    }
    if (j < end) {
        int sa = g_src[j];
        float wa = g_dinv[sa] * dn;
        float4 ua = load_row4(in, sa, lane);
        acc.x += ua.x * wa; acc.y += ua.y * wa;
        acc.z += ua.z * wa; acc.w += ua.w * wa;
    }
    float4 b = ((const float4*)bias)[lane];
    acc.x += acc2.x + b.x; acc.y += acc2.y + b.y;
    acc.z += acc2.z + b.z; acc.w += acc2.w + b.w;
    return acc;
}

// Layer 1: relu, emit fp16 (feeds gemm_f16A)
__global__ __launch_bounds__(256) void k_agg_f16(const __half* __restrict__ in,
                                                 __half* __restrict__ outh,
                                                 const float* __restrict__ bias) {
    int warp = (blockIdx.x * blockDim.x + threadIdx.x) >> 5;
    int lane = threadIdx.x & 31;
    if (warp >= NN) return;
    float4 acc = agg_core(in, warp, lane, bias);
    acc.x = fmaxf(acc.x, 0.f); acc.y = fmaxf(acc.y, 0.f);
    acc.z = fmaxf(acc.z, 0.f); acc.w = fmaxf(acc.w, 0.f);
    __half2 h0 = __floats2half2_rn(acc.x, acc.y);
    __half2 h1 = __floats2half2_rn(acc.z, acc.w);
    uint2 ph = make_uint2(*(uint32_t*)&h0, *(uint32_t*)&h1);
    ((uint2*)(outh + (size_t)warp * HIDF))[lane] = ph;
}

// Layer 2: fp32 out (final h), no relu
__global__ __launch_bounds__(256) void k_agg_f32(const __half* __restrict__ in,
                                                 float* __restrict__ out,
                                                 const float* __restrict__ bias) {
    int warp = (blockIdx.x * blockDim.x + threadIdx.x) >> 5;
    int lane = threadIdx.x & 31;
    if (warp >= NN) return;
    float4 acc = agg_core(in, warp, lane, bias);
    ((float4*)(out + (size_t)warp * HIDF))[lane] = acc;
}

// ---------------- global_add_pool: batch is sorted -> segmented sum ----------------
__global__ void k_pool(const float* __restrict__ h, const int* __restrict__ batch,
                       float* __restrict__ out) {
    int g = blockIdx.x;
    int t = threadIdx.x;
    int a = 0, b = NN;
    while (a < b) { int m = (a + b) >> 1; if (batch[m] < g) a = m + 1; else b = m; }
    int s = a;
    a = 0; b = NN;
    while (a < b) { int m = (a + b) >> 1; if (batch[m] < g + 1) a = m + 1; else b = m; }
    int e = a;
    float a0 = 0.f, a1 = 0.f, a2 = 0.f, a3 = 0.f;
    int n = s;
    for (; n + 3 < e; n += 4) {
        a0 += h[(size_t)n * HIDF + t];
        a1 += h[(size_t)(n + 1) * HIDF + t];
        a2 += h[(size_t)(n + 2) * HIDF + t];
        a3 += h[(size_t)(n + 3) * HIDF + t];
    }
    for (; n < e; n++) a0 += h[(size_t)n * HIDF + t];
    out[(size_t)g * HIDF + t] = (a0 + a1) + (a2 + a3);
}

// ---------------- launch ----------------
extern "C" void kernel_launch(void* const* d_in, const int* in_sizes, int n_in,
                              void* d_out, int out_size) {
    const float* x     = (const float*)d_in[0];
    const float* W1    = (const float*)d_in[1];
    const float* b1    = (const float*)d_in[2];
    const float* W2    = (const float*)d_in[3];
    const float* b2    = (const float*)d_in[4];
    const int*   ei    = (const int*)d_in[5];
    const int*   batch = (const int*)d_in[6];
    const int* row = ei;        // edge_index[0] = source
    const int* col = ei + NE;   // edge_index[1] = target

    float* out_hs = (float*)d_out;
    float* out_h  = (float*)d_out + (size_t)NG * HIDF;

    __half *g1, *h1h, *w1h, *w2h;
    cudaGetSymbolAddress((void**)&g1, g_g1);
    cudaGetSymbolAddress((void**)&h1h, g_h1h);
    cudaGetSymbolAddress((void**)&w1h, g_w1h);
    cudaGetSymbolAddress((void**)&w2h, g_w2h);

    cudaFuncSetAttribute(k_scan, cudaFuncAttributeMaxDynamicSharedMemorySize, NN * 4);

    // fork-join streams (created per call; see round-10 note on lifetime)
    cudaStream_t s2;
    cudaStreamCreateWithFlags(&s2, cudaStreamNonBlocking);
    cudaEvent_t evFork, evJoin;
    cudaEventCreateWithFlags(&evFork, cudaEventDisableTiming);
    cudaEventCreateWithFlags(&evJoin, cudaEventDisableTiming);

    cudaEventRecord(evFork, 0);
    cudaStreamWaitEvent(s2, evFork, 0);

    // branch B (s2): CSR build
    k_count<<<(NE / 2 + 255) / 256, 256, 0, s2>>>(col);
    k_scan<<<1, 1024, NN * 4, s2>>>();
    k_fill<<<(NE / 2 + 255) / 256, 256, 0, s2>>>(row, col);
    cudaEventRecord(evJoin, s2);

    const int GEMM_GRID = (NN + 127) / 128;  // 391
    const int AGG_GRID  = (NN + 7) / 8;      // 6250

    // branch A (origin): weights + layer-1 GEMM
    k_prepw<<<256, 256>>>(W1, W2);
    gemm_f32A<<<GEMM_GRID, 256>>>(x, w1h, g1, NN, INF_);

    // join: aggregation needs CSR
    cudaStreamWaitEvent(0, evJoin, 0);
    k_agg_f16<<<AGG_GRID, 256>>>(g1, h1h, b1);

    // layer 2
    gemm_f16A<<<GEMM_GRID, 256>>>(h1h, w2h, g1, NN, HIDF);
    k_agg_f32<<<AGG_GRID, 256>>>(g1, out_h, b2);

    // pooling
    k_pool<<<NG, 128>>>(out_h, batch, out_hs);
}

// round 13
// speedup vs baseline: 1.4600x; 1.1716x over previous
#include <cuda_runtime.h>
#include <cuda_fp16.h>
#include <cstdint>
#include <cstddef>

#define NN   50000
#define NE   640000
#define INF_ 512
#define HIDF 128
#define NG   256

// ---------------- device scratch (no allocations allowed) ----------------
__device__ int   g_cnt[NN];          // zero at load; k_scan restores to zero each launch
__device__ float g_dinv[NN];
__device__ int   g_rowptr[NN + 1];
__device__ int   g_rank[NE];
__device__ int   g_src[NE];
__device__ __half g_g1[(size_t)NN * HIDF];    // gemm outputs (fp16), reused both layers
__device__ __half g_h1h[(size_t)NN * HIDF];   // layer-1 agg output (fp16)
// transposed fp16 weights: Wt[n][k] = W[k][n]
__device__ __half g_w1h[128 * 512];
__device__ __half g_w2h[128 * 128];

// ---------------- helpers ----------------
__device__ __forceinline__ uint32_t smem_u32(const void* p) {
    uint32_t a;
    asm("{ .reg .u64 t; cvta.to.shared.u64 t, %1; cvt.u32.u64 %0, t; }" : "=r"(a) : "l"(p));
    return a;
}
__device__ __forceinline__ void ldsm_x4(uint32_t& r0, uint32_t& r1, uint32_t& r2, uint32_t& r3,
                                        uint32_t addr) {
    asm volatile("ldmatrix.sync.aligned.m8n8.x4.shared.b16 {%0,%1,%2,%3}, [%4];"
                 : "=r"(r0), "=r"(r1), "=r"(r2), "=r"(r3) : "r"(addr));
}
__device__ __forceinline__ void mma_f16(float* c, const uint32_t* a, const uint32_t* b) {
    asm volatile(
        "mma.sync.aligned.m16n8k16.row.col.f32.f16.f16.f32 "
        "{%0,%1,%2,%3}, {%4,%5,%6,%7}, {%8,%9}, {%0,%1,%2,%3};"
        : "+f"(c[0]), "+f"(c[1]), "+f"(c[2]), "+f"(c[3])
        : "r"(a[0]), "r"(a[1]), "r"(a[2]), "r"(a[3]), "r"(b[0]), "r"(b[1]));
}

// ---------------- preprocessing ----------------
// transpose/cast weights; consecutive threads read consecutive W elements
// (coalesced loads; strided fp16 stores are fire-and-forget)
__global__ void k_prepw(const float* __restrict__ W1, const float* __restrict__ W2) {
    int i = blockIdx.x * blockDim.x + threadIdx.x;
    if (i < 128 * 512) {
        int k = i >> 7, n = i & 127;           // coalesced read of W1[k][n]
        g_w1h[n * 512 + k] = __float2half_rn(W1[i]);
    }
    if (i < 128 * 128) {
        int k = i >> 7, n = i & 127;           // coalesced read of W2[k][n]
        g_w2h[n * 128 + k] = __float2half_rn(W2[i]);
    }
}

// count + record per-edge rank within destination (atomicAdd return value), 2 edges/thread
__global__ void k_count(const int* __restrict__ col) {
    int t = blockIdx.x * blockDim.x + threadIdx.x;
    if (t < NE / 2) {
        int2 c2 = ((const int2*)col)[t];
        int2 r;
        r.x = atomicAdd(&g_cnt[c2.x], 1);
        r.y = atomicAdd(&g_cnt[c2.y], 1);
        ((int2*)g_rank)[t] = r;
    }
}

// single-block scan, smem-staged for fully coalesced global access.
// Also restores g_cnt to zero for the next launch (invariant: zero at entry).
__global__ __launch_bounds__(1024) void k_scan() {
    extern __shared__ int sc[];   // NN ints = 200 000 B
    __shared__ int wsum[32];
    int t = threadIdx.x, lane = t & 31, w = t >> 5;
    for (int i = t; i < NN; i += 1024) {
        int c = g_cnt[i];
        sc[i] = c;
        g_dinv[i] = rsqrtf((float)(c + 1));  // +1 self-loop
        g_cnt[i] = 0;                        // restore invariant for next launch
    }
    __syncthreads();
    const int SEG = (NN + 1023) / 1024;  // 49
    int s0 = t * SEG, s1 = s0 + SEG;
    if (s1 > NN) s1 = NN;
    if (s0 > NN) s0 = NN;
    int s = 0;
    for (int i = s0; i < s1; i++) s += sc[i];
    int v = s;
    #pragma unroll
    for (int o = 1; o < 32; o <<= 1) {
        int u = __shfl_up_sync(0xFFFFFFFFu, v, o);
        if (lane >= o) v += u;
    }
    if (lane == 31) wsum[w] = v;
    __syncthreads();
    if (w == 0) {
        int x = wsum[lane];
        #pragma unroll
        for (int o = 1; o < 32; o <<= 1) {
            int u = __shfl_up_sync(0xFFFFFFFFu, x, o);
            if (lane >= o) x += u;
        }
        wsum[lane] = x;
    }
    __syncthreads();
    int P = v - s + (w > 0 ? wsum[w - 1] : 0);
    for (int i = s0; i < s1; i++) {
        int c = sc[i];
        sc[i] = P;     // in-place exclusive prefix
        P += c;
    }
    __syncthreads();
    for (int i = t; i < NN; i += 1024) g_rowptr[i] = sc[i];
    if (t == 0) g_rowptr[NN] = wsum[31];
}

// atomic-free fill using precomputed ranks, 2 edges/thread
__global__ void k_fill(const int* __restrict__ row, const int* __restrict__ col) {
    int t = blockIdx.x * blockDim.x + threadIdx.x;
    if (t < NE / 2) {
        int2 r2 = ((const int2*)row)[t];
        int2 c2 = ((const int2*)col)[t];
        int2 k2 = ((const int2*)g_rank)[t];
        g_src[g_rowptr[c2.x] + k2.x] = r2.x;
        g_src[g_rowptr[c2.y] + k2.y] = r2.y;
    }
}

// ---------------- HMMA GEMM: C[M,128] = A[M,K] @ Wt^T, fp16 out ----------------
#define ASTRIDE 40  // fp16 elems per smem row (80 B), conflict-free ldmatrix

template <bool F32A>
__device__ __forceinline__ void gemm_body(const void* __restrict__ Aptr,
                                          const __half* __restrict__ Bh,
                                          __half* __restrict__ C,
                                          int M, int K) {
    __shared__ __half sAh[128 * ASTRIDE];
    __shared__ __half sBh[128 * ASTRIDE];
    const int tid = threadIdx.x;
    const int wid = tid >> 5, lane = tid & 31;
    const int wm = (wid >> 1) * 32;
    const int wn = (wid & 1) * 64;
    const int g = lane >> 2, tig = lane & 3;
    const int row0 = blockIdx.x * 128;

    const uint32_t uAh = smem_u32(sAh);
    const uint32_t uBh = smem_u32(sBh);

    float c[2][8][4];
    #pragma unroll
    for (int mt = 0; mt < 2; mt++)
        #pragma unroll
        for (int nt = 0; nt < 8; nt++)
            #pragma unroll
            for (int q = 0; q < 4; q++) c[mt][nt][q] = 0.f;

    const int nch = K >> 5;

    float4 pa[4];
    uint4 pah[2];
    uint4 pbh[2];

    if (F32A) {
        const float* A = (const float*)Aptr;
        #pragma unroll
        for (int i = 0; i < 4; i++) {
            int q = i * 256 + tid;
            int r = q >> 3, c4 = q & 7;
            int gr = row0 + r;
            pa[i] = (gr < M) ? *(const float4*)(A + (size_t)gr * K + c4 * 4)
                             : make_float4(0.f, 0.f, 0.f, 0.f);
        }
    } else {
        const __half* Ah = (const __half*)Aptr;
        #pragma unroll
        for (int i = 0; i < 2; i++) {
            int q = i * 256 + tid;
            int r = q >> 2, c16 = q & 3;
            int gr = row0 + r;
            pah[i] = (gr < M) ? *(const uint4*)(Ah + (size_t)gr * K + c16 * 8)
                              : make_uint4(0, 0, 0, 0);
        }
    }
    #pragma unroll
    for (int i = 0; i < 2; i++) {
        int q = i * 256 + tid;
        int r = q >> 2, c16 = q & 3;
        pbh[i] = *(const uint4*)(Bh + (size_t)r * K + c16 * 8);
    }

    for (int ch = 0; ch < nch; ch++) {
        if (F32A) {
            #pragma unroll
            for (int i = 0; i < 4; i++) {
                int q = i * 256 + tid;
                int r = q >> 3, c4 = q & 7;
                float4 v = pa[i];
                __half2 h0 = __floats2half2_rn(v.x, v.y);
                __half2 h1 = __floats2half2_rn(v.z, v.w);
                int e = r * ASTRIDE + c4 * 4;
                *(uint32_t*)((char*)sAh + e * 2)     = *(uint32_t*)&h0;
                *(uint32_t*)((char*)sAh + e * 2 + 4) = *(uint32_t*)&h1;
            }
        } else {
            #pragma unroll
            for (int i = 0; i < 2; i++) {
                int q = i * 256 + tid;
                int r = q >> 2, c16 = q & 3;
                int e = r * ASTRIDE + c16 * 8;
                *(uint4*)((char*)sAh + e * 2) = pah[i];
            }
        }
        #pragma unroll
        for (int i = 0; i < 2; i++) {
            int q = i * 256 + tid;
            int r = q >> 2, c16 = q & 3;
            int e = r * ASTRIDE + c16 * 8;
            *(uint4*)((char*)sBh + e * 2) = pbh[i];
        }
        __syncthreads();

        if (ch + 1 < nch) {
            int k0 = (ch + 1) << 5;
            if (F32A) {
                const float* A = (const float*)Aptr;
                #pragma unroll
                for (int i = 0; i < 4; i++) {
                    int q = i * 256 + tid;
                    int r = q >> 3, c4 = q & 7;
                    int gr = row0 + r;
                    pa[i] = (gr < M) ? *(const float4*)(A + (size_t)gr * K + k0 + c4 * 4)
                                     : make_float4(0.f, 0.f, 0.f, 0.f);
                }
            } else {
                const __half* Ah = (const __half*)Aptr;
                #pragma unroll
                for (int i = 0; i < 2; i++) {
                    int q = i * 256 + tid;
                    int r = q >> 2, c16 = q & 3;
                    int gr = row0 + r;
                    pah[i] = (gr < M) ? *(const uint4*)(Ah + (size_t)gr * K + k0 + c16 * 8)
                                      : make_uint4(0, 0, 0, 0);
                }
            }
            #pragma unroll
            for (int i = 0; i < 2; i++) {
                int q = i * 256 + tid;
                int r = q >> 2, c16 = q & 3;
                pbh[i] = *(const uint4*)(Bh + (size_t)r * K + k0 + c16 * 8);
            }
        }

        #pragma unroll
        for (int ks = 0; ks < 2; ks++) {
            const int kc = ks * 16 + ((lane & 16) ? 8 : 0);
            uint32_t ah[2][4];
            #pragma unroll
            for (int mt = 0; mt < 2; mt++) {
                int r = wm + mt * 16 + (lane & 15);
                uint32_t off = (uint32_t)(r * ASTRIDE + kc) * 2;
                ldsm_x4(ah[mt][0], ah[mt][1], ah[mt][2], ah[mt][3], uAh + off);
            }
            uint32_t bh[8][2];
            const int kcb = ks * 16 + ((lane & 8) ? 8 : 0);
            #pragma unroll
            for (int nt4 = 0; nt4 < 4; nt4++) {
                int n = wn + nt4 * 16 + ((lane & 7) | ((lane & 16) ? 8 : 0));
                uint32_t off = (uint32_t)(n * ASTRIDE + kcb) * 2;
                ldsm_x4(bh[2 * nt4][0], bh[2 * nt4][1], bh[2 * nt4 + 1][0], bh[2 * nt4 + 1][1],
                        uBh + off);
            }
            #pragma unroll
            for (int mt = 0; mt < 2; mt++)
                #pragma unroll
                for (int nt = 0; nt < 8; nt++)
                    mma_f16(c[mt][nt], ah[mt], bh[nt]);
        }
        __syncthreads();
    }

    #pragma unroll
    for (int mt = 0; mt < 2; mt++) {
        int gr0 = row0 + wm + mt * 16 + g;
        int gr1 = gr0 + 8;
        #pragma unroll
        for (int nt = 0; nt < 8; nt++) {
            int cc = wn + nt * 8 + 2 * tig;
            if (gr0 < M) *(__half2*)(C + (size_t)gr0 * 128 + cc) = __floats2half2_rn(c[mt][nt][0], c[mt][nt][1]);
            if (gr1 < M) *(__half2*)(C + (size_t)gr1 * 128 + cc) = __floats2half2_rn(c[mt][nt][2], c[mt][nt][3]);
        }
    }
}

__global__ __launch_bounds__(256) void gemm_f32A(const float* __restrict__ A,
                                                 const __half* __restrict__ Bh,
                                                 __half* __restrict__ C, int M, int K) {
    gemm_body<true>(A, Bh, C, M, K);
}
__global__ __launch_bounds__(256) void gemm_f16A(const __half* __restrict__ Ah,
                                                 const __half* __restrict__ Bh,
                                                 __half* __restrict__ C, int M, int K) {
    gemm_body<false>(Ah, Bh, C, M, K);
}

// ---------------- aggregation: one warp per node, CSR gather of fp16 rows ----------------
__device__ __forceinline__ float4 load_row4(const __half* __restrict__ in, int node, int lane) {
    uint2 pv = ((const uint2*)(in + (size_t)node * HIDF))[lane];  // 4 halves
    float2 fa = __half22float2(*(__half2*)&pv.x);
    float2 fb = __half22float2(*(__half2*)&pv.y);
    return make_float4(fa.x, fa.y, fb.x, fb.y);
}

// Layer 1: relu, emit fp16 (feeds gemm_f16A) — simple serial gather (round-10 form)
__global__ __launch_bounds__(256) void k_agg_f16(const __half* __restrict__ in,
                                                 __half* __restrict__ outh,
                                                 const float* __restrict__ bias) {
    int warp = (blockIdx.x * blockDim.x + threadIdx.x) >> 5;
    int lane = threadIdx.x & 31;
    if (warp >= NN) return;
    float dn = g_dinv[warp];
    float4 v = load_row4(in, warp, lane);
    float s = dn * dn;
    float4 acc = make_float4(v.x * s, v.y * s, v.z * s, v.w * s);
    int beg = g_rowptr[warp], end = g_rowptr[warp + 1];
    for (int j = beg; j < end; j++) {
        int src = g_src[j];
        float w = g_dinv[src] * dn;
        float4 u = load_row4(in, src, lane);
        acc.x += u.x * w; acc.y += u.y * w;
        acc.z += u.z * w; acc.w += u.w * w;
    }
    float4 b = ((const float4*)bias)[lane];
    acc.x = fmaxf(acc.x + b.x, 0.f); acc.y = fmaxf(acc.y + b.y, 0.f);
    acc.z = fmaxf(acc.z + b.z, 0.f); acc.w = fmaxf(acc.w + b.w, 0.f);
    __half2 h0 = __floats2half2_rn(acc.x, acc.y);
    __half2 h1 = __floats2half2_rn(acc.z, acc.w);
    uint2 ph = make_uint2(*(uint32_t*)&h0, *(uint32_t*)&h1);
    ((uint2*)(outh + (size_t)warp * HIDF))[lane] = ph;
}

// Layer 2: fp32 out (final h), no relu — simple serial gather (round-10 form)
__global__ __launch_bounds__(256) void k_agg_f32(const __half* __restrict__ in,
                                                 float* __restrict__ out,
                                                 const float* __restrict__ bias) {
    int warp = (blockIdx.x * blockDim.x + threadIdx.x) >> 5;
    int lane = threadIdx.x & 31;
    if (warp >= NN) return;
    float dn = g_dinv[warp];
    float4 v = load_row4(in, warp, lane);
    float s = dn * dn;
    float4 acc = make_float4(v.x * s, v.y * s, v.z * s, v.w * s);
    int beg = g_rowptr[warp], end = g_rowptr[warp + 1];
    for (int j = beg; j < end; j++) {
        int src = g_src[j];
        float w = g_dinv[src] * dn;
        float4 u = load_row4(in, src, lane);
        acc.x += u.x * w; acc.y += u.y * w;
        acc.z += u.z * w; acc.w += u.w * w;
    }
    float4 b = ((const float4*)bias)[lane];
    acc.x += b.x; acc.y += b.y; acc.z += b.z; acc.w += b.w;
    ((float4*)(out + (size_t)warp * HIDF))[lane] = acc;
}

// ---------------- global_add_pool: batch is sorted -> segmented sum (round-10 form) ----------------
__global__ void k_pool(const float* __restrict__ h, const int* __restrict__ batch,
                       float* __restrict__ out) {
    int g = blockIdx.x;
    int t = threadIdx.x;
    int a = 0, b = NN;
    while (a < b) { int m = (a + b) >> 1; if (batch[m] < g) a = m + 1; else b = m; }
    int s = a;
    a = 0; b = NN;
    while (a < b) { int m = (a + b) >> 1; if (batch[m] < g + 1) a = m + 1; else b = m; }
    int e = a;
    float acc = 0.f;
    for (int n = s; n < e; n++) acc += h[(size_t)n * HIDF + t];
    out[(size_t)g * HIDF + t] = acc;
}

// ---------------- launch ----------------
extern "C" void kernel_launch(void* const* d_in, const int* in_sizes, int n_in,
                              void* d_out, int out_size) {
    const float* x     = (const float*)d_in[0];
    const float* W1    = (const float*)d_in[1];
    const float* b1    = (const float*)d_in[2];
    const float* W2    = (const float*)d_in[3];
    const float* b2    = (const float*)d_in[4];
    const int*   ei    = (const int*)d_in[5];
    const int*   batch = (const int*)d_in[6];
    const int* row = ei;        // edge_index[0] = source
    const int* col = ei + NE;   // edge_index[1] = target

    float* out_hs = (float*)d_out;
    float* out_h  = (float*)d_out + (size_t)NG * HIDF;

    __half *g1, *h1h, *w1h, *w2h;
    cudaGetSymbolAddress((void**)&g1, g_g1);
    cudaGetSymbolAddress((void**)&h1h, g_h1h);
    cudaGetSymbolAddress((void**)&w1h, g_w1h);
    cudaGetSymbolAddress((void**)&w2h, g_w2h);

    cudaFuncSetAttribute(k_scan, cudaFuncAttributeMaxDynamicSharedMemorySize, NN * 4);

    // fork-join streams (created per call; see round-10 note on lifetime)
    cudaStream_t s2;
    cudaStreamCreateWithFlags(&s2, cudaStreamNonBlocking);
    cudaEvent_t evFork, evJoin;
    cudaEventCreateWithFlags(&evFork, cudaEventDisableTiming);
    cudaEventCreateWithFlags(&evJoin, cudaEventDisableTiming);

    cudaEventRecord(evFork, 0);
    cudaStreamWaitEvent(s2, evFork, 0);

    // branch B (s2): CSR build
    k_count<<<(NE / 2 + 255) / 256, 256, 0, s2>>>(col);
    k_scan<<<1, 1024, NN * 4, s2>>>();
    k_fill<<<(NE / 2 + 255) / 256, 256, 0, s2>>>(row, col);
    cudaEventRecord(evJoin, s2);

    const int GEMM_GRID = (NN + 127) / 128;  // 391
    const int AGG_GRID  = (NN + 7) / 8;      // 6250

    // branch A (origin): weights + layer-1 GEMM
    k_prepw<<<256, 256>>>(W1, W2);
    gemm_f32A<<<GEMM_GRID, 256>>>(x, w1h, g1, NN, INF_);

    // join: aggregation needs CSR
    cudaStreamWaitEvent(0, evJoin, 0);
    k_agg_f16<<<AGG_GRID, 256>>>(g1, h1h, b1);

    // layer 2
    gemm_f16A<<<GEMM_GRID, 256>>>(h1h, w2h, g1, NN, HIDF);
    k_agg_f32<<<AGG_GRID, 256>>>(g1, out_h, b2);

    // pooling
    k_pool<<<NG, 128>>>(out_h, batch, out_hs);
}